// round 11
// baseline (speedup 1.0000x reference)
#include <cuda_runtime.h>
#include <cstdint>

#define B_  16
#define T_  128
#define C_  256
#define HW_ 1024

// ---------------- scratch (static device globals; no cudaMalloc allowed) ----
__device__ float g_WkT  [HW_ * C_];         // W_sK^T [HW, C]
__device__ float g_FsT  [B_ * C_ * HW_];    // F_s^T per batch [C, HW]
__device__ float g_Wp   [8 * C_ * C_];      // Wcomb split-K partials
__device__ float g_Wc   [C_ * C_];          // Wcomb = W_aQ @ WkT
__device__ float g_bc   [C_];               // bcomb = b_aQ @ WkT
__device__ float g_bsV  [C_];               // b_sV / T
__device__ float g_Qw   [B_ * T_  * C_];    // Qw = F_a @ Wcomb + bcomb
__device__ float g_QK   [B_ * T_  * HW_];   // QK -> S -> Kmat -> S_hat
__device__ float g_G    [B_ * T_  * C_];    // S_hat @ F_s
__device__ float g_O    [B_ * T_  * C_];    // G @ W_sV + b_sV/T
__device__ float g_H    [B_ * T_  * 3*C_];  // relu(O@W1+b1)
__device__ float g_u    [B_ * T_];
__device__ float g_v    [B_ * HW_];
__device__ int   g_iter_fallback = 100;

// ---------------- SIMT SGEMM, NN only (validated scalar core) ---------------
// C = rscale ⊙ (A @ B + bias), optional relu.
// A row-major [M,K] with row stride lda; B row-major [K,N].
// BM in {128,64}, BN=64, BK=16, 256 threads, (BM/16)x4 per-thread tile.
template <int BM>
__global__ __launch_bounds__(256) void sgemm(
    const float* __restrict__ A, const float* __restrict__ Bm,
    const float* __restrict__ bias, const float* __restrict__ rscale,
    float* __restrict__ C,
    int M, int N, int K, int lda,
    long long sA, long long sB, long long sC,
    int rsStride, int doRelu)
{
    constexpr int TM = BM / 16;
    __shared__ float As[16][BM];    // [k][m]
    __shared__ float Bs[16][68];    // [k][n]

    const int bz = blockIdx.z;
    const float* Ab = A  + (long long)bz * sA;
    const float* Bb = Bm + (long long)bz * sB;
    float*       Cb = C  + (long long)bz * sC;

    const int m0 = blockIdx.y * BM;
    const int n0 = blockIdx.x * 64;
    const int tid = threadIdx.x;
    const int tx = tid & 15;
    const int ty = tid >> 4;

    float acc[TM][4];
#pragma unroll
    for (int i = 0; i < TM; ++i)
#pragma unroll
        for (int j = 0; j < 4; ++j) acc[i][j] = 0.f;

    const int a_k4 = (tid & 3) << 2;
    const int a_m  = tid >> 2;

    for (int k0 = 0; k0 < K; k0 += 16) {
        // A tile BMx16 -> As[k][m]
#pragma unroll
        for (int r = 0; r < BM / 64; ++r) {
            int m = a_m + (r << 6);
            float4 va = *(const float4*)(Ab + (long long)(m0 + m) * lda + (k0 + a_k4));
            As[a_k4 + 0][m] = va.x; As[a_k4 + 1][m] = va.y;
            As[a_k4 + 2][m] = va.z; As[a_k4 + 3][m] = va.w;
        }
        // B tile 16x64 -> Bs[k][n]
        {
            int b_n4 = (tid & 15) << 2;
            int b_k  = tid >> 4;
            float4 vb = *(const float4*)(Bb + (long long)(k0 + b_k) * N + (n0 + b_n4));
            *(float4*)(&Bs[b_k][b_n4]) = vb;
        }
        __syncthreads();

#pragma unroll
        for (int k = 0; k < 16; ++k) {
            float af[TM], bf[4];
#pragma unroll
            for (int i = 0; i < TM; i += 4)
                *(float4*)&af[i] = *(const float4*)&As[k][ty * TM + i];
            *(float4*)&bf[0] = *(const float4*)&Bs[k][tx << 2];
#pragma unroll
            for (int i = 0; i < TM; ++i)
#pragma unroll
                for (int j = 0; j < 4; ++j)
                    acc[i][j] = fmaf(af[i], bf[j], acc[i][j]);
        }
        __syncthreads();
    }

#pragma unroll
    for (int i = 0; i < TM; ++i) {
        int m = m0 + ty * TM + i;
        float rs = rscale ? rscale[(long long)bz * rsStride + m] : 1.f;
        float vals[4];
#pragma unroll
        for (int j = 0; j < 4; ++j) {
            float x = acc[i][j];
            if (bias) x += bias[n0 + (tx << 2) + j];
            x *= rs;
            if (doRelu) x = fmaxf(x, 0.f);
            vals[j] = x;
        }
        *(float4*)(Cb + (long long)m * N + n0 + (tx << 2)) = *(float4*)vals;
    }
}

// ---------------- Wcomb split-K reduce: Wc = sum_z Wp[z] --------------------
__global__ __launch_bounds__(256) void wcomb_reduce(
    const float* __restrict__ Wp, float* __restrict__ Wc)
{
    int i = blockIdx.x * 256 + threadIdx.x;
    float s = 0.f;
#pragma unroll
    for (int z = 0; z < 8; ++z) s += Wp[z * (C_ * C_) + i];
    Wc[i] = s;
}

// ---------------- tiled transpose: out[Cc,R] = in[R,Cc]^T (per batch z) -----
__global__ __launch_bounds__(256) void transpose_k(
    const float* __restrict__ in, float* __restrict__ out,
    int R, int Cc, long long sIn, long long sOut)
{
    __shared__ float t[32][33];
    const float* ib = in  + (long long)blockIdx.z * sIn;
    float*       ob = out + (long long)blockIdx.z * sOut;
    const int r0 = blockIdx.y << 5;
    const int c0 = blockIdx.x << 5;
    const int lx = threadIdx.x & 31;
    const int ly = threadIdx.x >> 5;
#pragma unroll
    for (int i = ly; i < 32; i += 8)
        t[i][lx] = ib[(long long)(r0 + i) * Cc + (c0 + lx)];
    __syncthreads();
#pragma unroll
    for (int i = ly; i < 32; i += 8)
        ob[(long long)(c0 + i) * R + (r0 + lx)] = t[lx][i];
}

// ---------------- bias prep: bcomb[c] = b_aQ @ W_sK[c,:]; bsV = b_sV/T -------
__global__ __launch_bounds__(256) void prep_bias(
    const float* __restrict__ W_sK, const float* __restrict__ b_aQ,
    const float* __restrict__ b_sV,
    float* __restrict__ bc, float* __restrict__ bsV)
{
    __shared__ float red[256];
    const int c = blockIdx.x;
    const int tid = threadIdx.x;
    if (c == 0) bsV[tid] = b_sV[tid] * (1.f / (float)T_);
    const float* row = W_sK + (long long)c * HW_;
    float s = 0.f;
#pragma unroll
    for (int r = 0; r < 4; ++r) {
        int h = tid + (r << 8);
        s = fmaf(row[h], b_aQ[h], s);
    }
    red[tid] = s; __syncthreads();
    for (int st = 128; st; st >>= 1) { if (tid < st) red[tid] += red[tid + st]; __syncthreads(); }
    if (tid == 0) bc[c] = red[0];
}

// ---------------- masked softmax -> Kmat = exp(10*S - 10), in place ---------
__global__ __launch_bounds__(256) void softmax_kmat(
    float* __restrict__ ZK, const int* __restrict__ Ms)
{
    __shared__ float red[256];
    const int row = blockIdx.x;        // b*T + t
    const int b   = row >> 7;
    float* z = ZK + (long long)row * HW_;
    const int* mrow = Ms + b * HW_;
    const int tid = threadIdx.x;

    float zv[4]; int mv[4];
    float mx = -3.4e38f;
#pragma unroll
    for (int c = 0; c < 4; ++c) {
        int h = tid + (c << 8);
        zv[c] = z[h];
        mv[c] = mrow[h];
        if (mv[c]) mx = fmaxf(mx, zv[c]);
    }
    red[tid] = mx; __syncthreads();
    for (int s = 128; s; s >>= 1) { if (tid < s) red[tid] = fmaxf(red[tid], red[tid + s]); __syncthreads(); }
    mx = red[0]; __syncthreads();

    float ev[4], sum = 0.f;
#pragma unroll
    for (int c = 0; c < 4; ++c) {
        ev[c] = mv[c] ? expf(zv[c] - mx) : 0.f;
        sum += ev[c];
    }
    red[tid] = sum; __syncthreads();
    for (int s = 128; s; s >>= 1) { if (tid < s) red[tid] += red[tid + s]; __syncthreads(); }
    const float inv = 1.f / red[0];

#pragma unroll
    for (int c = 0; c < 4; ++c) {
        int h = tid + (c << 8);
        float S = ev[c] * inv;
        z[h] = expf(10.f * S - 10.f);     // exp(-(1-S)/0.1)
    }
}

// ---------------- cluster helpers --------------------------------------------
__device__ __forceinline__ uint32_t smem_u32(const void* p) {
    uint32_t a;
    asm("{ .reg .u64 t; cvta.to.shared.u64 t, %1; cvt.u32.u64 %0, t; }"
        : "=r"(a) : "l"(p));
    return a;
}
__device__ __forceinline__ void cluster_sync_() {
    asm volatile("barrier.cluster.arrive.aligned;" ::: "memory");
    asm volatile("barrier.cluster.wait.aligned;"  ::: "memory");
}
// push one float into peer-rank smem (weak cluster store)
__device__ __forceinline__ void st_peer_f32(uint32_t addr, uint32_t rank, float val) {
    uint32_t r;
    asm volatile("mapa.shared::cluster.u32 %0, %1, %2;" : "=r"(r) : "r"(addr), "r"(rank));
    asm volatile("st.shared::cluster.f32 [%0], %1;" :: "r"(r), "f"(val) : "memory");
}
// release-arrive on peer-rank mbarrier (orders this thread's prior cluster stores)
__device__ __forceinline__ void arrive_peer_release(uint32_t mbar, uint32_t rank) {
    uint32_t r;
    asm volatile("mapa.shared::cluster.u32 %0, %1, %2;" : "=r"(r) : "r"(mbar), "r"(rank));
    asm volatile("mbarrier.arrive.release.cluster.shared::cluster.b64 _, [%0];"
                 :: "r"(r) : "memory");
}
// acquire-wait (cluster scope) on local mbarrier phase parity
__device__ __forceinline__ void mbar_wait_parity_cluster(uint32_t mbar, uint32_t parity) {
    asm volatile(
        "{\n\t"
        ".reg .pred P;\n\t"
        "WAIT_%=:\n\t"
        "mbarrier.try_wait.parity.acquire.cluster.shared::cta.b64 P, [%0], %1, 0x989680;\n\t"
        "@P bra DONE_%=;\n\t"
        "bra WAIT_%=;\n\t"
        "DONE_%=:\n\t"
        "}"
        :: "r"(mbar), "r"(parity) : "memory");
}

// ---------------- Sinkhorn: validated compute; push-based mbarrier sync -----
// Per iteration, each of 128 active threads pushes its Kv partial to all 8
// CTAs' pslot[p][myrank][tid] and release-arrives on each peer's mbarrier
// (1024 arrivals/phase). Consumers acquire-wait their local mbarrier and sum
// 8 local smem values. Double-buffered slots (p = it&1); a peer can only push
// iter i+2 after consuming my iter i+1 arrivals, so slot reuse is safe.
// Epilogue writes S_hat = u ⊙ K ⊙ v in place (fused scale_uv; math proven R10).
__global__ void __cluster_dims__(8, 1, 1) __launch_bounds__(256, 1)
sinkhorn(float* __restrict__ Km, const int* __restrict__ Ms,
         const int* __restrict__ nIterPtr,
         float* __restrict__ gu, float* __restrict__ gv)
{
    extern __shared__ float sm[];
    // layout: [0..1] mbar (8B), [4..] Kt(128*129), u(128), v(128), bv(128),
    //         red(256), pslot(2*8*128)
    float* mbarf = sm;                  // 8 bytes
    float* Kt    = sm + 4;              // 128 * 129
    float* u     = Kt + 128 * 129;      // 128
    float* v     = u  + 128;            // 128
    float* bv    = v  + 128;            // 128
    float* red   = bv + 128;            // 256
    float* pslot = red + 256;           // 2 * 8 * 128

    const int rank = blockIdx.x;
    const int b    = blockIdx.y;
    const int h0   = rank << 7;
    const int tid  = threadIdx.x;

    const uint32_t mbar_a  = smem_u32(mbarf);
    const uint32_t pslot_a = smem_u32(pslot);

    if (tid == 0) {
        asm volatile("mbarrier.init.shared.b64 [%0], %1;"
                     :: "r"(mbar_a), "r"(1024u) : "memory");
    }

    const int* mrow = Ms + b * HW_;
    float msum = 0.f;
    for (int h = tid; h < HW_; h += 256) msum += (float)mrow[h];
    red[tid] = msum; __syncthreads();
    for (int s = 128; s; s >>= 1) { if (tid < s) red[tid] += red[tid + s]; __syncthreads(); }
    const float num_fg = red[0];
    __syncthreads();
    if (tid < 128) {
        bv[tid] = mrow[h0 + tid] ? 1.f / num_fg : 0.f;
        u[tid]  = 1.f / (float)T_;
    }

    float* Kb = Km + (long long)b * T_ * HW_ + h0;
    for (int idx = tid; idx < 128 * 128; idx += 256) {
        int t = idx >> 7, hl = idx & 127;
        Kt[t * 129 + hl] = Kb[(long long)t * HW_ + hl];
    }
    __syncthreads();
    // all 8 CTAs' mbarriers must be initialized before any peer push
    cluster_sync_();

    const int niter = *nIterPtr;
    const int col  = tid & 127;
    const int half = tid >> 7;

    for (int it = 0; it < niter; ++it) {
        const uint32_t p = (uint32_t)(it & 1);

        // phase 1: Ktu_h = sum_t K[t,h]*u[t]  (validated scalar walk)
        float s1 = 0.f;
        {
            const float* kp = Kt + (half << 6) * 129 + col;
            const float* up = u + (half << 6);
#pragma unroll 8
            for (int t = 0; t < 64; ++t) s1 = fmaf(kp[t * 129], up[t], s1);
        }
        red[tid] = s1; __syncthreads();
        if (tid < 128) {
            float ktu = red[tid] + red[tid + 128];
            float bb = bv[tid];
            v[tid] = (bb > 0.f) ? bb / ktu : 0.f;
        }
        __syncthreads();

        // phase 2: partial Kv_t over local columns (validated scalar walk)
        float s2 = 0.f;
        {
            const float* kp = Kt + col * 129 + (half << 6);
            const float* vp = v + (half << 6);
#pragma unroll 8
            for (int hh = 0; hh < 64; ++hh) s2 = fmaf(kp[hh], vp[hh], s2);
        }
        red[tid] = s2; __syncthreads();

        if (tid < 128) {
            const float pb = red[tid] + red[tid + 128];
            // push my partial into every CTA's pslot[p][rank][tid], then
            // release-arrive on each CTA's mbarrier
            const uint32_t dst = pslot_a + (((p << 10) + ((uint32_t)rank << 7) + (uint32_t)tid) << 2);
#pragma unroll
            for (int r = 0; r < 8; ++r) {
                st_peer_f32(dst, (uint32_t)r, pb);
                arrive_peer_release(mbar_a, (uint32_t)r);
            }
            // wait for all 1024 arrivals of this iteration (phase parity = p)
            mbar_wait_parity_cluster(mbar_a, p);
            float kv = 0.f;
#pragma unroll
            for (int r = 0; r < 8; ++r)
                kv += pslot[(p << 10) + (r << 7) + tid];
            u[tid] = (1.f / (float)T_) / kv;
        }
        __syncthreads();
    }

    if (tid < 128) {
        if (rank == 0) gu[b * T_ + tid] = u[tid];
        gv[b * HW_ + h0 + tid] = v[tid];
    }

    // epilogue: S_hat = u ⊙ K ⊙ v written back in place (fused scale_uv)
    for (int idx = tid; idx < 128 * 128; idx += 256) {
        int t = idx >> 7, hl = idx & 127;
        Kb[(long long)t * HW_ + hl] = u[t] * Kt[t * 129 + hl] * v[hl];
    }

    cluster_sync_();
}

// ---------------- driver ------------------------------------------------------
extern "C" void kernel_launch(void* const* d_in, const int* in_sizes, int n_in,
                              void* d_out, int out_size)
{
    const float* F_a  = (const float*)d_in[0];
    const float* F_s  = (const float*)d_in[1];
    const int*   M_s  = (const int*)  d_in[2];
    const float* W_aQ = (const float*)d_in[3];
    const float* b_aQ = (const float*)d_in[4];
    const float* W_sK = (const float*)d_in[5];
    // d_in[6] = b_sK : per-(b,t)-row logit constant, cancels in softmax over k
    const float* W_sV = (const float*)d_in[7];
    const float* b_sV = (const float*)d_in[8];
    const float* W1   = (const float*)d_in[9];
    const float* b1   = (const float*)d_in[10];
    const float* W2   = (const float*)d_in[11];
    const float* b2   = (const float*)d_in[12];
    float* y = (float*)d_out;

    float *WkT, *FsT, *Wp, *Wc, *bc, *bsV, *Qw, *QK, *G, *O, *H, *u, *v; int* itf;
    cudaGetSymbolAddress((void**)&WkT, g_WkT);
    cudaGetSymbolAddress((void**)&FsT, g_FsT);
    cudaGetSymbolAddress((void**)&Wp,  g_Wp);
    cudaGetSymbolAddress((void**)&Wc,  g_Wc);
    cudaGetSymbolAddress((void**)&bc,  g_bc);
    cudaGetSymbolAddress((void**)&bsV, g_bsV);
    cudaGetSymbolAddress((void**)&Qw,  g_Qw);
    cudaGetSymbolAddress((void**)&QK,  g_QK);
    cudaGetSymbolAddress((void**)&G,   g_G);
    cudaGetSymbolAddress((void**)&O,   g_O);
    cudaGetSymbolAddress((void**)&H,   g_H);
    cudaGetSymbolAddress((void**)&u,   g_u);
    cudaGetSymbolAddress((void**)&v,   g_v);
    cudaGetSymbolAddress((void**)&itf, g_iter_fallback);

    const int* iterp = (n_in > 13 && d_in[13]) ? (const int*)d_in[13]
                                               : (const int*)itf;

    // mbar(4) + Kt(128*129) + u/v/bv(384) + red(256) + pslot(2048) floats
    const int SK_SMEM = (4 + 128 * 129 + 384 + 256 + 2048) * 4;  // 76816 B
    cudaFuncSetAttribute(sinkhorn, cudaFuncAttributeMaxDynamicSharedMemorySize, SK_SMEM);

    // 0a) WkT = W_sK^T                 [256,1024] -> [1024,256]
    transpose_k<<<dim3(HW_ / 32, C_ / 32, 1), 256>>>(W_sK, WkT, C_, HW_, 0, 0);
    // 0b) FsT[b] = F_s[b]^T            [1024,256] -> [256,1024], batched
    transpose_k<<<dim3(C_ / 32, HW_ / 32, B_), 256>>>(
        F_s, FsT, HW_, C_, (long long)HW_ * C_, (long long)C_ * HW_);
    // 0c) bcomb + b_sV/T
    prep_bias<<<C_, 256>>>(W_sK, b_aQ, b_sV, bc, bsV);

    // 1) Wcomb split-K (grid 128) + reduce
    sgemm<64><<<dim3(4, 4, 8), 256>>>(
        W_aQ, WkT, nullptr, nullptr, Wp,
        C_, C_, 128, HW_,
        128LL, 128LL * C_, (long long)C_ * C_, 0, 0);
    wcomb_reduce<<<(C_ * C_) / 256, 256>>>(Wp, Wc);

    // 2) Qw = F_a @ Wcomb + bcomb      [2048,256] k=256 (NN, BM=64)
    sgemm<64><<<dim3(4, 32, 1), 256>>>(
        F_a, Wc, bc, nullptr, Qw, B_ * T_, C_, C_, C_, 0, 0, 0, 0, 0);

    // 3) QK[b] = Qw[b] @ FsT[b]        batched [128,1024] k=256 (NN, BM=64)
    sgemm<64><<<dim3(16, 2, B_), 256>>>(
        Qw, FsT, nullptr, nullptr, QK, T_, HW_, C_, C_,
        (long long)T_ * C_, (long long)C_ * HW_, (long long)T_ * HW_, 0, 0);

    // 4) masked softmax -> Kmat (in place)
    softmax_kmat<<<B_ * T_, 256>>>(QK, M_s);

    // 5) Sinkhorn OT -> u, v, and S_hat written in place (fused scale_uv)
    sinkhorn<<<dim3(8, B_), 256, SK_SMEM>>>(QK, M_s, iterp, u, v);

    // 6) G[b] = S_hat[b] @ F_s[b]      batched [128,256] k=1024 (NN, BM=64)
    sgemm<64><<<dim3(4, 2, B_), 256>>>(
        QK, F_s, nullptr, nullptr, G, T_, C_, HW_, HW_,
        (long long)T_ * HW_, (long long)HW_ * C_, (long long)T_ * C_, 0, 0);

    // 7) O = G @ W_sV + b_sV/T         [2048,256] k=256 (NN, BM=64)
    sgemm<64><<<dim3(4, 32, 1), 256>>>(
        G, W_sV, bsV, nullptr, O, B_ * T_, C_, C_, C_, 0, 0, 0, 0, 0);

    // 8) H = relu(O @ W1 + b1)         [2048,768] k=256 (NN, BM=64)
    sgemm<64><<<dim3(12, 32, 1), 256>>>(
        O, W1, b1, nullptr, H, B_ * T_, 3 * C_, C_, C_, 0, 0, 0, 0, 1);

    // 9) y = H @ W2 + b2 -> d_out      [2048,256] k=768 (NN, BM=64)
    sgemm<64><<<dim3(4, 32, 1), 256>>>(
        H, W2, b2, nullptr, y, B_ * T_, C_, 3 * C_, 3 * C_, 0, 0, 0, 0, 0);
}

// round 12
// speedup vs baseline: 1.4819x; 1.4819x over previous
#include <cuda_runtime.h>
#include <cstdint>

#define B_  16
#define T_  128
#define C_  256
#define HW_ 1024

// ---------------- scratch (static device globals; no cudaMalloc allowed) ----
__device__ float g_WkT  [HW_ * C_];         // W_sK^T [HW, C]
__device__ float g_FsT  [B_ * C_ * HW_];    // F_s^T per batch [C, HW]
__device__ float g_Wp   [8 * C_ * C_];      // Wcomb split-K partials
__device__ float g_Wc   [C_ * C_];          // Wcomb = W_aQ @ WkT
__device__ float g_bc   [C_];               // bcomb = b_aQ @ WkT
__device__ float g_bsV  [C_];               // b_sV / T
__device__ float g_Qw   [B_ * T_  * C_];    // Qw = F_a @ Wcomb + bcomb
__device__ float g_QK   [B_ * T_  * HW_];   // QK -> S -> Kmat -> S_hat
__device__ float g_G    [B_ * T_  * C_];    // S_hat @ F_s
__device__ float g_O    [B_ * T_  * C_];    // G @ W_sV + b_sV/T
__device__ float g_H    [B_ * T_  * 3*C_];  // relu(O@W1+b1)
__device__ float g_u    [B_ * T_];
__device__ float g_v    [B_ * HW_];
__device__ int   g_iter_fallback = 100;

// ---------------- SIMT SGEMM, NN only; double-buffered k-pipeline -----------
// C = rscale ⊙ (A @ B + bias), optional relu.
// A row-major [M,K] with row stride lda; B row-major [K,N].
// BM in {128,64}, BN=64, BK=16, 256 threads, (BM/16)x4 per-thread tile.
// Register-prefetch + 2-buffer smem: LDG for tile it+2 issues a full compute
// phase before its STS; one __syncthreads per k-iter. The end-of-iteration
// barrier guarantees all reads of buffer (it+1)&1 (used in iter it-1)
// completed before iter it stores to it. FMA order per accumulator is
// unchanged vs the validated kernel -> bit-identical results.
template <int BM>
__global__ __launch_bounds__(256) void sgemm(
    const float* __restrict__ A, const float* __restrict__ Bm,
    const float* __restrict__ bias, const float* __restrict__ rscale,
    float* __restrict__ C,
    int M, int N, int K, int lda,
    long long sA, long long sB, long long sC,
    int rsStride, int doRelu)
{
    constexpr int TM = BM / 16;
    constexpr int AR = BM / 64;
    __shared__ float As[2][16][BM];    // [buf][k][m]
    __shared__ float Bs[2][16][68];    // [buf][k][n]

    const int bz = blockIdx.z;
    const float* Ab = A  + (long long)bz * sA;
    const float* Bb = Bm + (long long)bz * sB;
    float*       Cb = C  + (long long)bz * sC;

    const int m0 = blockIdx.y * BM;
    const int n0 = blockIdx.x * 64;
    const int tid = threadIdx.x;
    const int tx = tid & 15;
    const int ty = tid >> 4;

    const int a_k4 = (tid & 3) << 2;
    const int a_m  = tid >> 2;
    const int b_n4 = (tid & 15) << 2;
    const int b_k  = tid >> 4;

    float acc[TM][4];
#pragma unroll
    for (int i = 0; i < TM; ++i)
#pragma unroll
        for (int j = 0; j < 4; ++j) acc[i][j] = 0.f;

    const int NIT = K >> 4;
    float4 ra[AR], rb;

    // prologue: tile 0 -> buf 0; prefetch tile 1 into regs
#pragma unroll
    for (int r = 0; r < AR; ++r)
        ra[r] = *(const float4*)(Ab + (long long)(m0 + a_m + (r << 6)) * lda + a_k4);
    rb = *(const float4*)(Bb + (long long)b_k * N + (n0 + b_n4));
#pragma unroll
    for (int r = 0; r < AR; ++r) {
        int m = a_m + (r << 6);
        As[0][a_k4 + 0][m] = ra[r].x; As[0][a_k4 + 1][m] = ra[r].y;
        As[0][a_k4 + 2][m] = ra[r].z; As[0][a_k4 + 3][m] = ra[r].w;
    }
    *(float4*)(&Bs[0][b_k][b_n4]) = rb;
    if (NIT > 1) {
#pragma unroll
        for (int r = 0; r < AR; ++r)
            ra[r] = *(const float4*)(Ab + (long long)(m0 + a_m + (r << 6)) * lda + (16 + a_k4));
        rb = *(const float4*)(Bb + (long long)(16 + b_k) * N + (n0 + b_n4));
    }
    __syncthreads();

    for (int it = 0; it < NIT; ++it) {
        const int cur = it & 1;
        if (it + 1 < NIT) {
            const int nxt = cur ^ 1;
            // store prefetched tile it+1 (buffer not read this iteration)
#pragma unroll
            for (int r = 0; r < AR; ++r) {
                int m = a_m + (r << 6);
                As[nxt][a_k4 + 0][m] = ra[r].x; As[nxt][a_k4 + 1][m] = ra[r].y;
                As[nxt][a_k4 + 2][m] = ra[r].z; As[nxt][a_k4 + 3][m] = ra[r].w;
            }
            *(float4*)(&Bs[nxt][b_k][b_n4]) = rb;
            if (it + 2 < NIT) {
                const int k0 = (it + 2) << 4;
#pragma unroll
                for (int r = 0; r < AR; ++r)
                    ra[r] = *(const float4*)(Ab + (long long)(m0 + a_m + (r << 6)) * lda + (k0 + a_k4));
                rb = *(const float4*)(Bb + (long long)(k0 + b_k) * N + (n0 + b_n4));
            }
        }
#pragma unroll
        for (int k = 0; k < 16; ++k) {
            float af[TM], bf[4];
#pragma unroll
            for (int i = 0; i < TM; i += 4)
                *(float4*)&af[i] = *(const float4*)&As[cur][k][ty * TM + i];
            *(float4*)&bf[0] = *(const float4*)&Bs[cur][k][tx << 2];
#pragma unroll
            for (int i = 0; i < TM; ++i)
#pragma unroll
                for (int j = 0; j < 4; ++j)
                    acc[i][j] = fmaf(af[i], bf[j], acc[i][j]);
        }
        __syncthreads();
    }

#pragma unroll
    for (int i = 0; i < TM; ++i) {
        int m = m0 + ty * TM + i;
        float rs = rscale ? rscale[(long long)bz * rsStride + m] : 1.f;
        float vals[4];
#pragma unroll
        for (int j = 0; j < 4; ++j) {
            float x = acc[i][j];
            if (bias) x += bias[n0 + (tx << 2) + j];
            x *= rs;
            if (doRelu) x = fmaxf(x, 0.f);
            vals[j] = x;
        }
        *(float4*)(Cb + (long long)m * N + n0 + (tx << 2)) = *(float4*)vals;
    }
}

// ---------------- Wcomb split-K reduce: Wc = sum_z Wp[z] --------------------
__global__ __launch_bounds__(256) void wcomb_reduce(
    const float* __restrict__ Wp, float* __restrict__ Wc)
{
    int i = blockIdx.x * 256 + threadIdx.x;
    float s = 0.f;
#pragma unroll
    for (int z = 0; z < 8; ++z) s += Wp[z * (C_ * C_) + i];
    Wc[i] = s;
}

// ---------------- tiled transpose: out[Cc,R] = in[R,Cc]^T (per batch z) -----
__global__ __launch_bounds__(256) void transpose_k(
    const float* __restrict__ in, float* __restrict__ out,
    int R, int Cc, long long sIn, long long sOut)
{
    __shared__ float t[32][33];
    const float* ib = in  + (long long)blockIdx.z * sIn;
    float*       ob = out + (long long)blockIdx.z * sOut;
    const int r0 = blockIdx.y << 5;
    const int c0 = blockIdx.x << 5;
    const int lx = threadIdx.x & 31;
    const int ly = threadIdx.x >> 5;
#pragma unroll
    for (int i = ly; i < 32; i += 8)
        t[i][lx] = ib[(long long)(r0 + i) * Cc + (c0 + lx)];
    __syncthreads();
#pragma unroll
    for (int i = ly; i < 32; i += 8)
        ob[(long long)(c0 + i) * R + (r0 + lx)] = t[lx][i];
}

// ---------------- bias prep: bcomb[c] = b_aQ @ W_sK[c,:]; bsV = b_sV/T -------
__global__ __launch_bounds__(256) void prep_bias(
    const float* __restrict__ W_sK, const float* __restrict__ b_aQ,
    const float* __restrict__ b_sV,
    float* __restrict__ bc, float* __restrict__ bsV)
{
    __shared__ float red[256];
    const int c = blockIdx.x;
    const int tid = threadIdx.x;
    if (c == 0) bsV[tid] = b_sV[tid] * (1.f / (float)T_);
    const float* row = W_sK + (long long)c * HW_;
    float s = 0.f;
#pragma unroll
    for (int r = 0; r < 4; ++r) {
        int h = tid + (r << 8);
        s = fmaf(row[h], b_aQ[h], s);
    }
    red[tid] = s; __syncthreads();
    for (int st = 128; st; st >>= 1) { if (tid < st) red[tid] += red[tid + st]; __syncthreads(); }
    if (tid == 0) bc[c] = red[0];
}

// ---------------- masked softmax -> Kmat = exp(10*S - 10), in place ---------
__global__ __launch_bounds__(256) void softmax_kmat(
    float* __restrict__ ZK, const int* __restrict__ Ms)
{
    __shared__ float red[256];
    const int row = blockIdx.x;        // b*T + t
    const int b   = row >> 7;
    float* z = ZK + (long long)row * HW_;
    const int* mrow = Ms + b * HW_;
    const int tid = threadIdx.x;

    float zv[4]; int mv[4];
    float mx = -3.4e38f;
#pragma unroll
    for (int c = 0; c < 4; ++c) {
        int h = tid + (c << 8);
        zv[c] = z[h];
        mv[c] = mrow[h];
        if (mv[c]) mx = fmaxf(mx, zv[c]);
    }
    red[tid] = mx; __syncthreads();
    for (int s = 128; s; s >>= 1) { if (tid < s) red[tid] = fmaxf(red[tid], red[tid + s]); __syncthreads(); }
    mx = red[0]; __syncthreads();

    float ev[4], sum = 0.f;
#pragma unroll
    for (int c = 0; c < 4; ++c) {
        ev[c] = mv[c] ? expf(zv[c] - mx) : 0.f;
        sum += ev[c];
    }
    red[tid] = sum; __syncthreads();
    for (int s = 128; s; s >>= 1) { if (tid < s) red[tid] += red[tid + s]; __syncthreads(); }
    const float inv = 1.f / red[0];

#pragma unroll
    for (int c = 0; c < 4; ++c) {
        int h = tid + (c << 8);
        float S = ev[c] * inv;
        z[h] = expf(10.f * S - 10.f);     // exp(-(1-S)/0.1)
    }
}

// ---------------- S_hat = u ⊙ Kmat ⊙ v, in place ----------------------------
__global__ __launch_bounds__(256) void scale_uv(
    float* __restrict__ Km, const float* __restrict__ u,
    const float* __restrict__ v)
{
    const int row = blockIdx.x;        // b*T + t
    const int b   = row >> 7;
    float* z = Km + (long long)row * HW_;
    const float* vb = v + b * HW_;
    const float ut = u[row];
    const int tid = threadIdx.x;
#pragma unroll
    for (int c = 0; c < 4; ++c) {
        int h = tid + (c << 8);
        z[h] = ut * z[h] * vb[h];
    }
}

// ---------------- cluster helpers --------------------------------------------
__device__ __forceinline__ uint32_t smem_u32(const void* p) {
    uint32_t a;
    asm("{ .reg .u64 t; cvta.to.shared.u64 t, %1; cvt.u32.u64 %0, t; }"
        : "=r"(a) : "l"(p));
    return a;
}
__device__ __forceinline__ void cluster_sync_() {
    asm volatile("barrier.cluster.arrive.aligned;" ::: "memory");
    asm volatile("barrier.cluster.wait.aligned;"  ::: "memory");
}
__device__ __forceinline__ float ld_peer_f32(uint32_t addr, uint32_t rank) {
    uint32_t r; float v;
    asm volatile("mapa.shared::cluster.u32 %0, %1, %2;" : "=r"(r) : "r"(addr), "r"(rank));
    asm volatile("ld.shared::cluster.f32 %0, [%1];"     : "=f"(v) : "r"(r));
    return v;
}

// ---------------- Sinkhorn (round-9 benched configuration, verbatim) --------
__global__ void __cluster_dims__(8, 1, 1) __launch_bounds__(256, 1)
sinkhorn(const float* __restrict__ Km, const int* __restrict__ Ms,
         const int* __restrict__ nIterPtr,
         float* __restrict__ gu, float* __restrict__ gv)
{
    extern __shared__ float sm[];
    float* Kt   = sm;                   // 128 * 129
    float* u    = Kt + 128 * 129;       // 128
    float* v    = u  + 128;             // 128
    float* bv   = v  + 128;             // 128
    float* red  = bv + 128;             // 256
    float* pbuf = red + 256;            // 2 * 128

    const int rank = blockIdx.x;
    const int b    = blockIdx.y;
    const int h0   = rank << 7;
    const int tid  = threadIdx.x;

    const int* mrow = Ms + b * HW_;
    float msum = 0.f;
    for (int h = tid; h < HW_; h += 256) msum += (float)mrow[h];
    red[tid] = msum; __syncthreads();
    for (int s = 128; s; s >>= 1) { if (tid < s) red[tid] += red[tid + s]; __syncthreads(); }
    const float num_fg = red[0];
    __syncthreads();
    if (tid < 128) {
        bv[tid] = mrow[h0 + tid] ? 1.f / num_fg : 0.f;
        u[tid]  = 1.f / (float)T_;
    }

    const float* Kb = Km + (long long)b * T_ * HW_ + h0;
    for (int idx = tid; idx < 128 * 128; idx += 256) {
        int t = idx >> 7, hl = idx & 127;
        Kt[t * 129 + hl] = Kb[(long long)t * HW_ + hl];
    }
    __syncthreads();

    const int niter = *nIterPtr;
    const int col  = tid & 127;
    const int half = tid >> 7;
    const uint32_t pbuf_addr = smem_u32(pbuf);

    for (int it = 0; it < niter; ++it) {
        const int p = it & 1;

        float s1 = 0.f;
        {
            const float* kp = Kt + (half << 6) * 129 + col;
            const float* up = u + (half << 6);
#pragma unroll 8
            for (int t = 0; t < 64; ++t) s1 = fmaf(kp[t * 129], up[t], s1);
        }
        red[tid] = s1; __syncthreads();
        if (tid < 128) {
            float ktu = red[tid] + red[tid + 128];
            float bb = bv[tid];
            v[tid] = (bb > 0.f) ? bb / ktu : 0.f;
        }
        __syncthreads();

        float s2 = 0.f;
        {
            const float* kp = Kt + col * 129 + (half << 6);
            const float* vp = v + (half << 6);
#pragma unroll 8
            for (int hh = 0; hh < 64; ++hh) s2 = fmaf(kp[hh], vp[hh], s2);
        }
        red[tid] = s2; __syncthreads();
        if (tid < 128) pbuf[(p << 7) + tid] = red[tid] + red[tid + 128];

        cluster_sync_();

        if (tid < 128) {
            float kv = 0.f;
#pragma unroll
            for (int r = 0; r < 8; ++r)
                kv += ld_peer_f32(pbuf_addr + (((p << 7) + tid) << 2), (uint32_t)r);
            u[tid] = (1.f / (float)T_) / kv;
        }
        __syncthreads();
    }

    if (tid < 128) {
        if (rank == 0) gu[b * T_ + tid] = u[tid];
        gv[b * HW_ + h0 + tid] = v[tid];
    }
    cluster_sync_();
}

// ---------------- driver ------------------------------------------------------
extern "C" void kernel_launch(void* const* d_in, const int* in_sizes, int n_in,
                              void* d_out, int out_size)
{
    const float* F_a  = (const float*)d_in[0];
    const float* F_s  = (const float*)d_in[1];
    const int*   M_s  = (const int*)  d_in[2];
    const float* W_aQ = (const float*)d_in[3];
    const float* b_aQ = (const float*)d_in[4];
    const float* W_sK = (const float*)d_in[5];
    // d_in[6] = b_sK : per-(b,t)-row logit constant, cancels in softmax over k
    const float* W_sV = (const float*)d_in[7];
    const float* b_sV = (const float*)d_in[8];
    const float* W1   = (const float*)d_in[9];
    const float* b1   = (const float*)d_in[10];
    const float* W2   = (const float*)d_in[11];
    const float* b2   = (const float*)d_in[12];
    float* y = (float*)d_out;

    float *WkT, *FsT, *Wp, *Wc, *bc, *bsV, *Qw, *QK, *G, *O, *H, *u, *v; int* itf;
    cudaGetSymbolAddress((void**)&WkT, g_WkT);
    cudaGetSymbolAddress((void**)&FsT, g_FsT);
    cudaGetSymbolAddress((void**)&Wp,  g_Wp);
    cudaGetSymbolAddress((void**)&Wc,  g_Wc);
    cudaGetSymbolAddress((void**)&bc,  g_bc);
    cudaGetSymbolAddress((void**)&bsV, g_bsV);
    cudaGetSymbolAddress((void**)&Qw,  g_Qw);
    cudaGetSymbolAddress((void**)&QK,  g_QK);
    cudaGetSymbolAddress((void**)&G,   g_G);
    cudaGetSymbolAddress((void**)&O,   g_O);
    cudaGetSymbolAddress((void**)&H,   g_H);
    cudaGetSymbolAddress((void**)&u,   g_u);
    cudaGetSymbolAddress((void**)&v,   g_v);
    cudaGetSymbolAddress((void**)&itf, g_iter_fallback);

    const int* iterp = (n_in > 13 && d_in[13]) ? (const int*)d_in[13]
                                               : (const int*)itf;

    const int SK_SMEM = (128 * 129 + 128 * 3 + 256 + 256) * 4;  // 69632 B
    cudaFuncSetAttribute(sinkhorn, cudaFuncAttributeMaxDynamicSharedMemorySize, SK_SMEM);

    // 0a) WkT = W_sK^T                 [256,1024] -> [1024,256]
    transpose_k<<<dim3(HW_ / 32, C_ / 32, 1), 256>>>(W_sK, WkT, C_, HW_, 0, 0);
    // 0b) FsT[b] = F_s[b]^T            [1024,256] -> [256,1024], batched
    transpose_k<<<dim3(C_ / 32, HW_ / 32, B_), 256>>>(
        F_s, FsT, HW_, C_, (long long)HW_ * C_, (long long)C_ * HW_);
    // 0c) bcomb + b_sV/T
    prep_bias<<<C_, 256>>>(W_sK, b_aQ, b_sV, bc, bsV);

    // 1) Wcomb split-K (grid 128) + reduce
    sgemm<64><<<dim3(4, 4, 8), 256>>>(
        W_aQ, WkT, nullptr, nullptr, Wp,
        C_, C_, 128, HW_,
        128LL, 128LL * C_, (long long)C_ * C_, 0, 0);
    wcomb_reduce<<<(C_ * C_) / 256, 256>>>(Wp, Wc);

    // 2) Qw = F_a @ Wcomb + bcomb      [2048,256] k=256 (NN, BM=64)
    sgemm<64><<<dim3(4, 32, 1), 256>>>(
        F_a, Wc, bc, nullptr, Qw, B_ * T_, C_, C_, C_, 0, 0, 0, 0, 0);

    // 3) QK[b] = Qw[b] @ FsT[b]        batched [128,1024] k=256 (NN, BM=64)
    sgemm<64><<<dim3(16, 2, B_), 256>>>(
        Qw, FsT, nullptr, nullptr, QK, T_, HW_, C_, C_,
        (long long)T_ * C_, (long long)C_ * HW_, (long long)T_ * HW_, 0, 0);

    // 4) masked softmax -> Kmat (in place)
    softmax_kmat<<<B_ * T_, 256>>>(QK, M_s);

    // 5) Sinkhorn OT -> u, v
    sinkhorn<<<dim3(8, B_), 256, SK_SMEM>>>(QK, M_s, iterp, u, v);

    // 6) S_hat = u ⊙ Kmat ⊙ v (in place)
    scale_uv<<<B_ * T_, 256>>>(QK, u, v);

    // 7) G[b] = S_hat[b] @ F_s[b]      batched [128,256] k=1024 (NN, BM=64)
    sgemm<64><<<dim3(4, 2, B_), 256>>>(
        QK, F_s, nullptr, nullptr, G, T_, C_, HW_, HW_,
        (long long)T_ * HW_, (long long)HW_ * C_, (long long)T_ * C_, 0, 0);

    // 8) O = G @ W_sV + b_sV/T         [2048,256] k=256 (NN, BM=64)
    sgemm<64><<<dim3(4, 32, 1), 256>>>(
        G, W_sV, bsV, nullptr, O, B_ * T_, C_, C_, C_, 0, 0, 0, 0, 0);

    // 9) H = relu(O @ W1 + b1)         [2048,768] k=256 (NN, BM=64)
    sgemm<64><<<dim3(12, 32, 1), 256>>>(
        O, W1, b1, nullptr, H, B_ * T_, 3 * C_, C_, C_, 0, 0, 0, 0, 1);

    // 10) y = H @ W2 + b2 -> d_out     [2048,256] k=768 (NN, BM=64)
    sgemm<64><<<dim3(4, 32, 1), 256>>>(
        H, W2, b2, nullptr, y, B_ * T_, C_, 3 * C_, 3 * C_, 0, 0, 0, 0, 0);
}